// round 7
// baseline (speedup 1.0000x reference)
#include <cuda_runtime.h>
#include <cuda_bf16.h>
#include <cstdint>

// ---------------------------------------------------------------------------
// BlockDiagonalGRU via mma.sync tf32, warp-specialized (sm_100 base).
// R7: producer warp + mbarrier stage ring replaces the per-chunk
//     __syncthreads lockstep. No CTA-wide barrier in the mainloop.
//   Grid: 1024 CTAs = nb(8) x ctile(16 x 32 cols) x mtile(8 x 128 rows).
//   288 thr: warps 0-7 consumers (4m x 2n, warp tile 32x16 per gate),
//   warp 8 producer (cp.async fills, pointer-increment addressing).
//   2 CTAs/SM. Accs: R (fused), Z (fused), IN, HN -> 64 f32/thread.
//   3-stage ring, TK=32. A and W fed as raw fp32 (HW tf32 RZ truncation),
//   compensated by (1+2^-11)^2 in the epilogue.
// ---------------------------------------------------------------------------

namespace {

constexpr int HID = 4096;
constexpr int BS  = 512;
constexpr int G3  = 1536;

constexpr int STRIDE = 36;                      // words per 32-k row (+4 pad)
constexpr int A_ROWS = 128;
constexpr int B_ROWS = 96;                      // 3 gates x 32
constexpr int A_FB    = A_ROWS * STRIDE * 4;    // 18432 B
constexpr int STAGE_B = (A_ROWS + B_ROWS) * STRIDE * 4;  // 32256 B
constexpr int STAGES  = 3;
constexpr int HDR     = 128;                    // mbarrier header
constexpr int SMEM_BYTES = HDR + STAGES * STAGE_B;  // 96896 B

constexpr float COMP = 1.0009765625f;           // (1+2^-11)^2 ~= 1+2^-10

__device__ __forceinline__ uint32_t smem_u32(const void* p) {
    uint32_t a;
    asm("{ .reg .u64 t; cvta.to.shared.u64 t, %1; cvt.u32.u64 %0, t; }"
        : "=r"(a) : "l"(p));
    return a;
}
__device__ __forceinline__ float tanh_ap(float x) {
    float y;
    asm("tanh.approx.f32 %0, %1;" : "=f"(y) : "f"(x));
    return y;
}
__device__ __forceinline__ float sig_ap(float x) {
    return fmaf(0.5f, tanh_ap(0.5f * x), 0.5f);
}
__device__ __forceinline__ void cp16(uint32_t dst, const void* src) {
    asm volatile("cp.async.cg.shared.global [%0], [%1], 16;"
                 :: "r"(dst), "l"(src) : "memory");
}
__device__ __forceinline__ void ldsm4(uint32_t* r, uint32_t addr) {
    asm volatile("ldmatrix.sync.aligned.m8n8.x4.shared.b16 {%0,%1,%2,%3}, [%4];"
                 : "=r"(r[0]), "=r"(r[1]), "=r"(r[2]), "=r"(r[3]) : "r"(addr));
}
__device__ __forceinline__ void mma8(float* c, const uint32_t* a, const uint32_t* b) {
    asm volatile(
        "mma.sync.aligned.m16n8k8.row.col.f32.tf32.tf32.f32 "
        "{%0,%1,%2,%3}, {%4,%5,%6,%7}, {%8,%9}, {%0,%1,%2,%3};"
        : "+f"(c[0]), "+f"(c[1]), "+f"(c[2]), "+f"(c[3])
        : "r"(a[0]), "r"(a[1]), "r"(a[2]), "r"(a[3]), "r"(b[0]), "r"(b[1]));
}
__device__ __forceinline__ void mbar_init(uint32_t a, uint32_t n) {
    asm volatile("mbarrier.init.shared.b64 [%0], %1;" :: "r"(a), "r"(n) : "memory");
}
__device__ __forceinline__ void mbar_arrive(uint32_t a) {
    asm volatile("mbarrier.arrive.shared.b64 _, [%0];" :: "r"(a) : "memory");
}
__device__ __forceinline__ void cpasync_arrive_noinc(uint32_t a) {
    asm volatile("cp.async.mbarrier.arrive.noinc.shared.b64 [%0];"
                 :: "r"(a) : "memory");
}
__device__ __forceinline__ void mbar_wait(uint32_t addr, uint32_t parity) {
    uint32_t done;
    asm volatile(
        "{\n\t.reg .pred p;\n\t"
        "mbarrier.try_wait.parity.acquire.cta.shared::cta.b64 p, [%1], %2;\n\t"
        "selp.b32 %0, 1, 0, p;\n\t}"
        : "=r"(done) : "r"(addr), "r"(parity) : "memory");
    if (!done) {
        asm volatile(
            "{\n\t.reg .pred P1;\n\t"
            "W_%=:\n\t"
            "mbarrier.try_wait.parity.acquire.cta.shared::cta.b64 P1, [%0], %1, 0x989680;\n\t"
            "@P1 bra.uni D_%=;\n\t"
            "bra.uni W_%=;\n\t"
            "D_%=:\n\t}"
            :: "r"(addr), "r"(parity) : "memory");
    }
}

}  // namespace

__global__ __launch_bounds__(288, 2)
void BlockDiagonalGRU_kernel(
    const float* __restrict__ x, const float* __restrict__ h,
    const float* __restrict__ Wih, const float* __restrict__ Whh,
    const float* __restrict__ bih, const float* __restrict__ bhh,
    float* __restrict__ out)
{
    extern __shared__ float smf[];
    const uint32_t smb = smem_u32(smf);

    const int tid  = threadIdx.x;
    const int wid  = tid >> 5;
    const int lane = tid & 31;

    const int m  = blockIdx.x & 7;
    const int c  = (blockIdx.x >> 3) & 15;      // 16 col tiles of 32
    const int nb = blockIdx.x >> 7;

    // mbarriers: full[s] at smb + s*8, empty[s] at smb + 24 + s*8
    if (tid == 0) {
        #pragma unroll
        for (int s = 0; s < STAGES; ++s) {
            mbar_init(smb + s * 8, 32);          // full: producer cp.async arrives
            mbar_init(smb + 24 + s * 8, 256);    // empty: consumer thread arrives
        }
    }
    __syncthreads();

    const float* Abase[2] = { x + (size_t)(m * 128) * HID + nb * BS,
                              h + (size_t)(m * 128) * HID + nb * BS };
    const float* Wbase[2] = { Wih + (size_t)nb * G3 * BS,
                              Whh + (size_t)nb * G3 * BS };

    // ================= producer warp =================
    if (wid == 8) {
        const int r0 = lane >> 3;        // 0..3
        const int q  = lane & 7;         // 0..7
        const uint32_t sA0 = (uint32_t)(r0 * STRIDE * 4 + q * 16);
        const uint32_t sW0 = (uint32_t)(A_FB + r0 * STRIDE * 4 + q * 16);

        int st = 0, ph = 1;
        for (int i = 0; i < 32; ++i) {
            mbar_wait(smb + 24 + st * 8, (uint32_t)ph);   // wait empty

            const int p  = i >> 4;
            const int kc = (i & 15) * 32;
            const uint32_t sb0 = smb + HDR + (uint32_t)(st * STAGE_B);

            // A tile: rows r0+4*ii, ii = 0..31
            {
                const float* g = Abase[p] + kc + (size_t)r0 * HID + q * 4;
                uint32_t sa = sb0 + sA0;
                #pragma unroll 8
                for (int ii = 0; ii < 32; ++ii) {
                    cp16(sa, g);
                    g  += 4 * HID;
                    sa += 4 * STRIDE * 4;
                }
            }
            // W tiles: 3 gate segments, rows w0+4*ii within each gate (ii<8)
            {
                uint32_t sw = sb0 + sW0;
                #pragma unroll
                for (int g3 = 0; g3 < 3; ++g3) {
                    const float* g = Wbase[p] + kc +
                        (size_t)(g3 * BS + c * 32 + r0) * BS + q * 4;
                    #pragma unroll 8
                    for (int ii = 0; ii < 8; ++ii) {
                        cp16(sw, g);
                        g  += 4 * BS;
                        sw += 4 * STRIDE * 4;
                    }
                }
            }
            cpasync_arrive_noinc(smb + st * 8);           // full arrive on完成
            if (++st == STAGES) { st = 0; ph ^= 1; }
        }
        return;
    }

    // ================= consumer warps (0-7) =================
    const int gq = lane >> 2;
    const int t4 = lane & 3;
    const int wr = (wid >> 1) * 32;   // 4 m-groups of 32 rows
    const int wc = (wid & 1) * 16;    // 2 n-groups of 16 cols

    const uint32_t laneA =
        (uint32_t)(((((lane >> 3) & 1) * 8 + (lane & 7)) * STRIDE + (lane >> 4) * 4) * 4)
        + (uint32_t)(wr * STRIDE * 4);
    const uint32_t laneB =
        (uint32_t)((((lane >> 4) * 8 + (lane & 7)) * STRIDE + ((lane >> 3) & 1) * 4) * 4)
        + (uint32_t)A_FB + (uint32_t)(wc * STRIDE * 4);

    float accR[2][2][4] = {}, accZ[2][2][4] = {};
    float accI[2][2][4] = {}, accH[2][2][4] = {};

    uint32_t fa[2][2][4];   // A frags, ks-double-buffered
    uint32_t fb[3][4];      // B frags, per-ks

    int st = 0, ph = 0;
    for (int i = 0; i < 32; ++i) {
        mbar_wait(smb + st * 8, (uint32_t)ph);            // wait full

        const uint32_t sA = smb + HDR + (uint32_t)(st * STAGE_B);
        const uint32_t aA = sA + laneA;
        const uint32_t aB = sA + laneB;

        ldsm4(fa[0][0], aA);
        ldsm4(fa[0][1], aA + (uint32_t)(16 * STRIDE * 4));

        float (*accN)[2][4] = (i >> 4) ? accH : accI;

        #pragma unroll
        for (int ks = 0; ks < 4; ++ks) {
            const int cur = ks & 1;
            const uint32_t ko = (uint32_t)(ks * 32);
            ldsm4(fb[0], aB + ko);
            ldsm4(fb[1], aB + ko + (uint32_t)(32 * STRIDE * 4));
            ldsm4(fb[2], aB + ko + (uint32_t)(64 * STRIDE * 4));
            if (ks < 3) {
                const int nxt = cur ^ 1;
                ldsm4(fa[nxt][0], aA + ko + 32u);
                ldsm4(fa[nxt][1], aA + ko + 32u + (uint32_t)(16 * STRIDE * 4));
            }
            #pragma unroll
            for (int n2 = 0; n2 < 2; ++n2) {
                mma8(accR[0][n2], fa[cur][0], fb[0] + n2 * 2);
                mma8(accR[1][n2], fa[cur][1], fb[0] + n2 * 2);
                mma8(accZ[0][n2], fa[cur][0], fb[1] + n2 * 2);
                mma8(accZ[1][n2], fa[cur][1], fb[1] + n2 * 2);
                mma8(accN[0][n2], fa[cur][0], fb[2] + n2 * 2);
                mma8(accN[1][n2], fa[cur][1], fb[2] + n2 * 2);
            }
        }
        mbar_arrive(smb + 24 + st * 8);                   // release stage
        if (++st == STAGES) { st = 0; ph ^= 1; }
    }

    // ---- fused GRU epilogue ----
    const float* bi = bih + nb * G3;
    const float* bh = bhh + nb * G3;

    #pragma unroll
    for (int mf = 0; mf < 2; ++mf) {
        #pragma unroll
        for (int nf = 0; nf < 2; ++nf) {
            const int colb = c * 32 + wc + nf * 8 + 2 * t4;   // col in 512 block
            const int rowb = m * 128 + wr + mf * 16 + gq;
            #pragma unroll
            for (int half = 0; half < 2; ++half) {
                const int row = rowb + 8 * half;
                const int i0  = 2 * half;
                const size_t goff = (size_t)row * HID + nb * BS + colb;
                const float2 hv = *reinterpret_cast<const float2*>(h + goff);
                float res[2];
                #pragma unroll
                for (int k = 0; k < 2; ++k) {
                    const int cb = colb + k;
                    const float rp = accR[mf][nf][i0 + k] * COMP
                                   + __ldg(bi + cb) + __ldg(bh + cb);
                    const float zp = accZ[mf][nf][i0 + k] * COMP
                                   + __ldg(bi + BS + cb) + __ldg(bh + BS + cb);
                    const float ip = accI[mf][nf][i0 + k] * COMP + __ldg(bi + 2 * BS + cb);
                    const float hp = accH[mf][nf][i0 + k] * COMP + __ldg(bh + 2 * BS + cb);
                    const float r  = sig_ap(rp);
                    const float z  = sig_ap(zp);
                    const float ng = tanh_ap(fmaf(r, hp, ip));
                    const float hval = (k == 0) ? hv.x : hv.y;
                    res[k] = fmaf(z, hval - ng, ng);
                }
                *reinterpret_cast<float2*>(out + goff) = make_float2(res[0], res[1]);
            }
        }
    }
}

extern "C" void kernel_launch(void* const* d_in, const int* in_sizes, int n_in,
                              void* d_out, int out_size) {
    (void)in_sizes; (void)n_in; (void)out_size;
    cudaFuncSetAttribute(BlockDiagonalGRU_kernel,
                         cudaFuncAttributeMaxDynamicSharedMemorySize, SMEM_BYTES);
    BlockDiagonalGRU_kernel<<<1024, 288, SMEM_BYTES>>>(
        (const float*)d_in[0], (const float*)d_in[1],
        (const float*)d_in[2], (const float*)d_in[3],
        (const float*)d_in[4], (const float*)d_in[5],
        (float*)d_out);
}